// round 11
// baseline (speedup 1.0000x reference)
#include <cuda_runtime.h>
#include <cstdint>
#include <math.h>

#define BQ    4
#define NN    160
#define TT    512
#define NWU   16                    // 512/32 u32 words
#define MAXMB 48                    // tracked set bits of M (mean ~25.6)
#define TSTR  17                    // padded tag row stride (words)
#define GS    64                    // blocks per batch
#define TOTB  (GS * BQ)             // 256 (<= 2 per SM: all co-resident)
#define PAIRS (NN * (NN - 1) / 2)   // 12720
#define NTH   512
#define WPB   (2560 / GS)           // 40 tag-words packed per block

__device__ unsigned          g_tag32[BQ][NN][NWU];
__device__ volatile unsigned g_arrive[BQ];          // zero-init at load; reset per run
__device__ double            g_part[TOTB];
__device__ unsigned          g_ctr = 0;

__device__ __forceinline__ unsigned pack32(const float4* p)
{
    float4 v[8];
    #pragma unroll
    for (int q = 0; q < 8; ++q) v[q] = p[q];     // 8 independent LDG.128
    unsigned bits = 0;
    #pragma unroll
    for (int q = 0; q < 8; ++q) {
        bits |= (v[q].x > 0.5f ? 1u : 0u) << (q * 4 + 0);
        bits |= (v[q].y > 0.5f ? 1u : 0u) << (q * 4 + 1);
        bits |= (v[q].z > 0.5f ? 1u : 0u) << (q * 4 + 2);
        bits |= (v[q].w > 0.5f ? 1u : 0u) << (q * 4 + 3);
    }
    return bits;
}

// ---------------------------------------------------------------------------
// Single kernel: distributed pack + grid spin-sync + prep + pairs + finalize.
// grid=(GS,BQ)x512 = 256 blocks, ~2 per SM for stall overlap.
// ---------------------------------------------------------------------------
__global__ void __launch_bounds__(NTH)
lrl_all(const float* __restrict__ scores, const float* __restrict__ M,
        const float* __restrict__ api,   const int*   __restrict__ preds,
        float* __restrict__ out)
{
    const int g    = blockIdx.x;
    const int b    = blockIdx.y;
    const int tid  = threadIdx.x;
    const int wid  = tid >> 5;
    const int lane = tid & 31;

    __shared__ unsigned      s_tag[NN][TSTR];
    __shared__ unsigned      s_M[NWU];
    __shared__ float         s_sc[NN];
    __shared__ float         s_il[NN];
    __shared__ int           s_mbits[MAXMB];
    __shared__ int           s_first[MAXMB];
    __shared__ unsigned      s_rows[MAXMB][5];
    __shared__ unsigned      s_mjlo[NN], s_mjhi[NN];
    __shared__ unsigned      s_amlo[NN], s_amhi[NN];
    __shared__ unsigned char s_et[MAXMB * NN];
    __shared__ float         s_cU[NN];
    __shared__ float         s_S[NN + 1], s_C[NN + 1];
    __shared__ float         s_totS[5], s_totC[5];
    __shared__ int           s_mcnt;
    __shared__ float         s_invMc;
    __shared__ float         s_red[16];
    __shared__ int           s_last;
    __shared__ double        s_dred[TOTB];

    // ---- P-1: pack own tag slice -> global; M/scores/il locally -------------
    if (tid < WPB) {
        const int word = g * WPB + tid;          // 40 words of this batch
        const int r = word >> 4, w = word & 15;
        const int pred = preds[b * NN + r];
        g_tag32[b][r][w] =
            pack32((const float4*)(api + (size_t)pred * TT + w * 32));
        __threadfence();                          // make store device-visible
    } else if (tid < WPB + NWU) {
        const int w = tid - WPB;
        s_M[w] = pack32((const float4*)(M + b * TT + w * 32));
    } else if (tid >= 192 && tid < 352) {
        s_sc[tid - 192] = scores[b * NN + (tid - 192)];
    } else if (tid >= 352) {
        s_il[tid - 352] = 1.0f / log2f((float)(tid - 352 + 2));
    }
    __syncthreads();
    if (tid == 0) atomicAdd((unsigned*)&g_arrive[b], 1u);

    // ---- P1 (overlaps other blocks' packing): mbits scan + pair decode ------
    if (wid == 0) {
        const unsigned mw = (lane < NWU) ? s_M[lane] : 0u;
        const int cnt = __popc(mw);
        int inc = cnt;
        #pragma unroll
        for (int o = 1; o < 32; o <<= 1) {
            const int v = __shfl_up_sync(0xffffffffu, inc, o);
            if (lane >= o) inc += v;
        }
        int off = inc - cnt;
        const int total = __shfl_sync(0xffffffffu, inc, 31);
        unsigned mm = mw;
        while (mm) {
            const int bp = __ffs(mm) - 1;
            mm &= mm - 1;
            if (off < MAXMB) s_mbits[off] = lane * 32 + bp;
            ++off;
        }
        if (lane == 0) {
            s_mcnt  = (total > MAXMB) ? MAXMB : total;
            s_invMc = 1.0f / (float)(total + 1);
        }
    }

    int   pri = 0, prj = 0, prv = 0;
    float plam = 0.0f;
    {
        const int chunk = (PAIRS + GS - 1) / GS;            // 199
        const int p  = g * chunk + tid;
        const int p1 = min(g * chunk + chunk, PAIRS);
        prv = (p < p1);
        if (prv) {
            int j = (int)((1.0f + sqrtf(8.0f * (float)p + 1.0f)) * 0.5f);
            while (((j * (j - 1)) >> 1) > p) --j;
            while (((j * (j + 1)) >> 1) <= p) ++j;
            pri = p - ((j * (j - 1)) >> 1);
            prj = j;
            plam = 1.0f / (1.0f + expf(s_sc[pri] - s_sc[prj]));
        }
    }

    // ---- grid spin-sync: wait for this batch's 64 pack slices ----------------
    if (tid == 0) {
        while (g_arrive[b] < GS) { /* volatile poll */ }
        __threadfence();                          // acquire
    }
    __syncthreads();

    // ---- P0: stage packed tags (coalesced uint4) ------------------------------
    {
        const uint4* src = (const uint4*)g_tag32[b];       // 640 uint4
        for (int e = tid; e < 640; e += NTH) {
            const uint4 v = src[e];
            const int f = e * 4;
            const int r = f >> 4, w = f & 15;
            s_tag[r][w]     = v.x;
            s_tag[r][w + 1] = v.y;
            s_tag[r][w + 2] = v.z;
            s_tag[r][w + 3] = v.w;
        }
    }
    __syncthreads();

    const int mcnt = s_mcnt;

    // ---- P2: row bitmaps — warp-tasks (m, word5), all 16 warps ----------------
    for (int task = wid; task < mcnt * 5; task += 16) {
        const int m  = task / 5;
        const int w5 = task - m * 5;
        const int t  = s_mbits[m];
        const unsigned flag =
            (s_tag[w5 * 32 + lane][t >> 5] >> (t & 31)) & 1u;
        const unsigned bal = __ballot_sync(0xffffffffu, flag);
        if (lane == 0) s_rows[m][w5] = bal;
    }
    __syncthreads();

    // ---- P3: first occurrence (tid<mcnt) || zero scatter masks (others) -------
    if (tid < mcnt) {
        int first = 1000;
        #pragma unroll
        for (int w = 4; w >= 0; --w) {
            const unsigned bits = s_rows[tid][w];
            if (bits) first = w * 32 + __ffs(bits) - 1;
        }
        s_first[tid] = first;
    } else if (tid >= 64 && tid < 64 + NN) {
        s_mjlo[tid - 64] = 0u; s_mjhi[tid - 64] = 0u;
    } else if (tid >= 256 && tid < 256 + NN) {
        s_amlo[tid - 256] = 0u; s_amhi[tid - 256] = 0u;
    }
    __syncthreads();

    // ---- P4: mj scatter (all warps) ; cU (w0-4) || alive e-fill (w5-15) -------
    for (int task = wid; task < mcnt * 5; task += 16) {
        const int m  = task / 5;
        const int jw = task - m * 5;
        const unsigned word = s_rows[m][jw];
        if ((word >> lane) & 1u) {
            const int j = jw * 32 + lane;
            if (m < 32) atomicOr(&s_mjlo[j], 1u << m);
            else        atomicOr(&s_mjhi[j], 1u << (m - 32));
        }
    }
    if (wid < 5) {
        if (tid < NN) {
            int cu = 0;
            #pragma unroll 4
            for (int m = 0; m < mcnt; ++m) cu += (s_first[m] > tid);
            s_cU[tid] = (float)cu;
        }
    } else {
        for (int m = wid - 5; m < mcnt; m += 11) {
            const int first = s_first[m];
            const int iend  = min(first + 1, NN - 1);
            for (int i = lane; i <= iend; i += 32) {
                int nxt = 1000;
                const int r = i + 1;
                if (r < NN) {
                    int wd = r >> 5;
                    unsigned bits = s_rows[m][wd] & (0xffffffffu << (r & 31));
                    while (!bits && ++wd < 5) bits = s_rows[m][wd];
                    if (bits) nxt = wd * 32 + __ffs(bits) - 1;
                }
                const int e = (i == 0 && first <= NN - 2) ? 0 : min(nxt + 1, NN);
                s_et[m * NN + i] = (unsigned char)e;
                if (m < 32) atomicOr(&s_amlo[i], 1u << m);
                else        atomicOr(&s_amhi[i], 1u << (m - 32));
            }
        }
    }
    __syncthreads();

    // ---- P5: warp-parallel S/C scan (5 chunks) + offset fixup ------------------
    if (wid < 5) {
        const int idx = wid * 32 + lane;
        float a = s_il[idx];
        float d = s_cU[idx] * s_il[idx];
        #pragma unroll
        for (int o = 1; o < 32; o <<= 1) {
            const float ta = __shfl_up_sync(0xffffffffu, a, o);
            const float td = __shfl_up_sync(0xffffffffu, d, o);
            if (lane >= o) { a += ta; d += td; }
        }
        s_S[idx + 1] = a;
        s_C[idx + 1] = d;
        if (lane == 31) { s_totS[wid] = a; s_totC[wid] = d; }
    }
    __syncthreads();
    if (tid < NN) {
        float offS = 0.0f, offC = 0.0f;
        #pragma unroll
        for (int w = 0; w < 4; ++w)
            if (w < (tid >> 5)) { offS += s_totS[w]; offC += s_totC[w]; }
        s_S[tid + 1] += offS;
        s_C[tid + 1] += offC;
    }
    if (tid == 0) { s_S[0] = 0.0f; s_C[0] = 0.0f; }
    __syncthreads();

    // ---- PE: one pair per thread; sparse alive∩¬tag[j] loop ---------------------
    float acc = 0.0f;
    if (prv) {
        const int i = pri, j = prj;
        const float Si = s_S[i], Sj = s_S[j];
        unsigned long long w =
              (unsigned long long)(s_amlo[i] & ~s_mjlo[j])
            | ((unsigned long long)(s_amhi[i] & ~s_mjhi[j]) << 32);
        float acc2 = 0.0f;
        while (w) {
            const int m = __ffsll(w) - 1;
            w &= w - 1;
            const int e = s_et[m * NN + i];
            acc2 += fminf(s_S[e], Sj) - Si;
        }
        acc = plam * ((s_C[j] - s_C[i]) - acc2);
    }

    // ---- block reduce + deterministic finalize -----------------------------------
    #pragma unroll
    for (int off = 16; off; off >>= 1)
        acc += __shfl_down_sync(0xffffffffu, acc, off);
    if (lane == 0) s_red[wid] = acc;
    __syncthreads();
    if (tid < 32) {
        float v = (tid < 16) ? s_red[tid] : 0.0f;
        #pragma unroll
        for (int off = 8; off; off >>= 1)
            v += __shfl_down_sync(0xffffffffu, v, off);
        if (tid == 0) {
            g_part[b * GS + g] = (double)v * (double)s_invMc;
            __threadfence();
            const unsigned old = atomicInc(&g_ctr, TOTB - 1);   // wraps to 0
            s_last = (old == TOTB - 1);
        }
    }
    __syncthreads();

    if (s_last) {
        if (tid < BQ) *((unsigned*)&g_arrive[tid]) = 0;   // reset for next replay
        if (tid == 0) __threadfence();
        __syncthreads();
        if (tid < TOTB) s_dred[tid] = g_part[tid];
        __syncthreads();
        if (tid < 128) s_dred[tid] += s_dred[tid + 128];
        __syncthreads();
        if (tid < 64) s_dred[tid] += s_dred[tid + 64];
        __syncthreads();
        if (tid < 32) {
            double v = s_dred[tid] + s_dred[tid + 32];
            #pragma unroll
            for (int off = 16; off; off >>= 1)
                v += __shfl_down_sync(0xffffffffu, v, off);
            if (tid == 0)
                out[0] = (float)(v / (double)((NN + 1) * BQ));
        }
    }
}

// ---------------------------------------------------------------------------
extern "C" void kernel_launch(void* const* d_in, const int* in_sizes, int n_in,
                              void* d_out, int out_size)
{
    const float* y_scores = (const float*)d_in[0];   // (B, N) f32
    const float* M        = (const float*)d_in[1];   // (B, T) f32 {0,1}
    const float* api      = (const float*)d_in[2];   // (NUM_API, T) f32 {0,1}
    const int*   preds    = (const int*)  d_in[3];   // (B, N) i32
    float* out = (float*)d_out;

    lrl_all<<<dim3(GS, BQ), NTH>>>(y_scores, M, api, preds, out);
}

// round 12
// speedup vs baseline: 1.1235x; 1.1235x over previous
#include <cuda_runtime.h>
#include <cstdint>
#include <math.h>

#define BQ    4
#define NN    160
#define TT    512
#define NWU   16                    // 512/32 u32 words
#define MAXMB 48                    // tracked set bits of M (mean ~25.6)
#define GS    32                    // blocks per batch
#define TOTB  (GS * BQ)             // 128 (all co-resident, 1/SM)
#define PAIRS (NN * (NN - 1) / 2)   // 12720
#define NTH   512

__device__ unsigned          g_rows32[BQ][MAXMB][5];   // transposed tag info
__device__ volatile unsigned g_arrive[BQ];             // zero-init; reset per run
__device__ double            g_part[TOTB];
__device__ unsigned          g_ctr = 0;

__device__ __forceinline__ unsigned pack32(const float4* p)
{
    float4 v[8];
    #pragma unroll
    for (int q = 0; q < 8; ++q) v[q] = p[q];
    unsigned bits = 0;
    #pragma unroll
    for (int q = 0; q < 8; ++q) {
        bits |= (v[q].x > 0.5f ? 1u : 0u) << (q * 4 + 0);
        bits |= (v[q].y > 0.5f ? 1u : 0u) << (q * 4 + 1);
        bits |= (v[q].z > 0.5f ? 1u : 0u) << (q * 4 + 2);
        bits |= (v[q].w > 0.5f ? 1u : 0u) << (q * 4 + 3);
    }
    return bits;
}

// ---------------------------------------------------------------------------
// Single kernel, transposed pack: only the ~26 M-bit row-bitmaps ever leave
// a block. grid=(GS,BQ)x512, one block per SM.
// ---------------------------------------------------------------------------
__global__ void __launch_bounds__(NTH)
lrl_all(const float* __restrict__ scores, const float* __restrict__ M,
        const float* __restrict__ api,   const int*   __restrict__ preds,
        float* __restrict__ out)
{
    const int g    = blockIdx.x;
    const int b    = blockIdx.y;
    const int tid  = threadIdx.x;
    const int wid  = tid >> 5;
    const int lane = tid & 31;

    __shared__ float         s_sc[NN];
    __shared__ float         s_il[NN];
    __shared__ int           s_mbits[MAXMB];
    __shared__ int           s_first[MAXMB];
    __shared__ unsigned      s_rows[MAXMB][5];
    __shared__ unsigned      s_mjlo[NN], s_mjhi[NN];
    __shared__ unsigned      s_amlo[NN], s_amhi[NN];
    __shared__ unsigned char s_et[MAXMB * NN];
    __shared__ float         s_cU[NN];
    __shared__ float         s_S[NN + 1], s_C[NN + 1];
    __shared__ float         s_totS[5], s_totC[5];
    __shared__ int           s_mcnt;
    __shared__ float         s_invMc;
    __shared__ float         s_red[16];
    __shared__ int           s_last;
    __shared__ double        s_dred[TOTB];

    // ---- PA: warp0 packs M (registers) + mbits scan; others: sc/il/zeroing --
    if (wid == 0) {
        unsigned mw = 0;
        if (lane < NWU)
            mw = pack32((const float4*)(M + b * TT + lane * 32));
        const int cnt = __popc(mw);
        int inc = cnt;
        #pragma unroll
        for (int o = 1; o < 32; o <<= 1) {
            const int v = __shfl_up_sync(0xffffffffu, inc, o);
            if (lane >= o) inc += v;
        }
        int off = inc - cnt;                              // exclusive prefix
        const int total = __shfl_sync(0xffffffffu, inc, 31);
        unsigned mm = mw;
        while (mm) {
            const int bp = __ffs(mm) - 1;
            mm &= mm - 1;
            if (off < MAXMB) s_mbits[off] = lane * 32 + bp;
            ++off;
        }
        if (lane == 0) {
            s_mcnt  = (total > MAXMB) ? MAXMB : total;
            s_invMc = 1.0f / (float)(total + 1);
        }
    } else if (tid >= 32 && tid < 192) {
        s_sc[tid - 32] = scores[b * NN + (tid - 32)];
    } else if (tid >= 192 && tid < 352) {
        s_il[tid - 192] = 1.0f / log2f((float)(tid - 192 + 2));
    } else {
        const int i = tid - 352;                          // 160 threads
        s_mjlo[i] = 0u; s_mjhi[i] = 0u;
        s_amlo[i] = 0u; s_amhi[i] = 0u;
    }
    __syncthreads();

    const int mcnt = s_mcnt;

    // ---- PB: transposed pack — warp-task (m, word5); <=1 task per warp -------
    {
        const int task = g * 16 + wid;                    // 0..511 across batch
        const int m = task / 5, w5 = task - m * 5;
        if (m < mcnt) {
            const int t = s_mbits[m];
            const int r = w5 * 32 + lane;                 // NN = 5*32 exactly
            const int pred = preds[b * NN + r];
            const float v = api[(size_t)pred * TT + t];   // scattered gather
            const unsigned bal = __ballot_sync(0xffffffffu, v > 0.5f);
            if (lane == 0) {
                g_rows32[b][m][w5] = bal;
                __threadfence();                          // release store
            }
        }
    }

    // ---- pair decode + lam (overlaps other blocks' packing) ------------------
    int   pri = 0, prj = 0, prv = 0;
    float plam = 0.0f;
    {
        const int chunk = (PAIRS + GS - 1) / GS;          // 398
        const int p  = g * chunk + tid;
        const int p1 = min(g * chunk + chunk, PAIRS);
        prv = (p < p1);
        if (prv) {
            int j = (int)((1.0f + sqrtf(8.0f * (float)p + 1.0f)) * 0.5f);
            while (((j * (j - 1)) >> 1) > p) --j;
            while (((j * (j + 1)) >> 1) <= p) ++j;
            pri = p - ((j * (j - 1)) >> 1);
            prj = j;
            plam = 1.0f / (1.0f + expf(s_sc[pri] - s_sc[prj]));
        }
    }
    __syncthreads();
    if (tid == 0) atomicAdd((unsigned*)&g_arrive[b], 1u);

    // ---- grid spin-sync: all GS blocks of this batch packed -------------------
    if (tid == 0) {
        while (g_arrive[b] < GS) { /* volatile poll */ }
        __threadfence();                                  // acquire
    }
    __syncthreads();

    // ---- PC: read row bitmaps (<=240 words) -----------------------------------
    if (tid < mcnt * 5) {
        const int m = tid / 5, w5 = tid - m * 5;
        s_rows[m][w5] = g_rows32[b][m][w5];
    }
    __syncthreads();

    // ---- PD: first occurrence per M-bit ----------------------------------------
    if (tid < mcnt) {
        int first = 1000;
        #pragma unroll
        for (int w = 4; w >= 0; --w) {
            const unsigned bits = s_rows[tid][w];
            if (bits) first = w * 32 + __ffs(bits) - 1;
        }
        s_first[tid] = first;
    }
    __syncthreads();

    // ---- PE: mj scatter (all warps) ; cU (w0-4) || alive e-fill (w5-15) -------
    for (int task = wid; task < mcnt * 5; task += 16) {
        const int m  = task / 5;
        const int jw = task - m * 5;
        const unsigned word = s_rows[m][jw];
        if ((word >> lane) & 1u) {
            const int j = jw * 32 + lane;
            if (m < 32) atomicOr(&s_mjlo[j], 1u << m);
            else        atomicOr(&s_mjhi[j], 1u << (m - 32));
        }
    }
    if (wid < 5) {
        if (tid < NN) {
            int cu = 0;
            #pragma unroll 4
            for (int m = 0; m < mcnt; ++m) cu += (s_first[m] > tid);
            s_cU[tid] = (float)cu;
        }
    } else {
        for (int m = wid - 5; m < mcnt; m += 11) {
            const int first = s_first[m];
            const int iend  = min(first + 1, NN - 1);
            for (int i = lane; i <= iend; i += 32) {
                int nxt = 1000;
                const int r = i + 1;
                if (r < NN) {
                    int wd = r >> 5;
                    unsigned bits = s_rows[m][wd] & (0xffffffffu << (r & 31));
                    while (!bits && ++wd < 5) bits = s_rows[m][wd];
                    if (bits) nxt = wd * 32 + __ffs(bits) - 1;
                }
                const int e = (i == 0 && first <= NN - 2) ? 0 : min(nxt + 1, NN);
                s_et[m * NN + i] = (unsigned char)e;
                if (m < 32) atomicOr(&s_amlo[i], 1u << m);
                else        atomicOr(&s_amhi[i], 1u << (m - 32));
            }
        }
    }
    __syncthreads();

    // ---- PF: warp-parallel S/C scan (5 chunks) + offset fixup ------------------
    if (wid < 5) {
        const int idx = wid * 32 + lane;
        float a = s_il[idx];
        float d = s_cU[idx] * s_il[idx];
        #pragma unroll
        for (int o = 1; o < 32; o <<= 1) {
            const float ta = __shfl_up_sync(0xffffffffu, a, o);
            const float td = __shfl_up_sync(0xffffffffu, d, o);
            if (lane >= o) { a += ta; d += td; }
        }
        s_S[idx + 1] = a;
        s_C[idx + 1] = d;
        if (lane == 31) { s_totS[wid] = a; s_totC[wid] = d; }
    }
    __syncthreads();
    if (tid < NN) {
        float offS = 0.0f, offC = 0.0f;
        #pragma unroll
        for (int w = 0; w < 4; ++w)
            if (w < (tid >> 5)) { offS += s_totS[w]; offC += s_totC[w]; }
        s_S[tid + 1] += offS;
        s_C[tid + 1] += offC;
    }
    if (tid == 0) { s_S[0] = 0.0f; s_C[0] = 0.0f; }
    __syncthreads();

    // ---- PG: one pair per thread; sparse alive∩¬tag[j] loop ---------------------
    float acc = 0.0f;
    if (prv) {
        const int i = pri, j = prj;
        const float Si = s_S[i], Sj = s_S[j];
        unsigned long long w =
              (unsigned long long)(s_amlo[i] & ~s_mjlo[j])
            | ((unsigned long long)(s_amhi[i] & ~s_mjhi[j]) << 32);
        float acc2 = 0.0f;
        while (w) {
            const int m = __ffsll(w) - 1;
            w &= w - 1;
            const int e = s_et[m * NN + i];
            acc2 += fminf(s_S[e], Sj) - Si;
        }
        acc = plam * ((s_C[j] - s_C[i]) - acc2);
    }

    // ---- block reduce + deterministic finalize -----------------------------------
    #pragma unroll
    for (int off = 16; off; off >>= 1)
        acc += __shfl_down_sync(0xffffffffu, acc, off);
    if (lane == 0) s_red[wid] = acc;
    __syncthreads();
    if (tid < 32) {
        float v = (tid < 16) ? s_red[tid] : 0.0f;
        #pragma unroll
        for (int off = 8; off; off >>= 1)
            v += __shfl_down_sync(0xffffffffu, v, off);
        if (tid == 0) {
            g_part[b * GS + g] = (double)v * (double)s_invMc;
            __threadfence();
            const unsigned old = atomicInc(&g_ctr, TOTB - 1);   // wraps to 0
            s_last = (old == TOTB - 1);
        }
    }
    __syncthreads();

    if (s_last) {
        if (tid < BQ) *((unsigned*)&g_arrive[tid]) = 0;   // reset for next replay
        if (tid == 0) __threadfence();
        __syncthreads();
        if (tid < TOTB) s_dred[tid] = g_part[tid];
        __syncthreads();
        if (tid < 64) s_dred[tid] += s_dred[tid + 64];
        __syncthreads();
        if (tid < 32) {
            double v = s_dred[tid] + s_dred[tid + 32];
            #pragma unroll
            for (int off = 16; off; off >>= 1)
                v += __shfl_down_sync(0xffffffffu, v, off);
            if (tid == 0)
                out[0] = (float)(v / (double)((NN + 1) * BQ));
        }
    }
}

// ---------------------------------------------------------------------------
extern "C" void kernel_launch(void* const* d_in, const int* in_sizes, int n_in,
                              void* d_out, int out_size)
{
    const float* y_scores = (const float*)d_in[0];   // (B, N) f32
    const float* M        = (const float*)d_in[1];   // (B, T) f32 {0,1}
    const float* api      = (const float*)d_in[2];   // (NUM_API, T) f32 {0,1}
    const int*   preds    = (const int*)  d_in[3];   // (B, N) i32
    float* out = (float*)d_out;

    lrl_all<<<dim3(GS, BQ), NTH>>>(y_scores, M, api, preds, out);
}

// round 13
// speedup vs baseline: 1.1254x; 1.0017x over previous
#include <cuda_runtime.h>
#include <cstdint>
#include <math.h>

#define BQ    4
#define NN    160
#define TT    512
#define NWU   16                    // 512/32 u32 words
#define MAXMB 48                    // tracked set bits of M (mean ~25.6)
#define GS    32                    // blocks per batch
#define TOTB  (GS * BQ)             // 128 (all co-resident, 1/SM)
#define PAIRS (NN * (NN - 1) / 2)   // 12720
#define NTH   512

__device__ unsigned          g_rowsT[BQ][TT][8];   // raw-t row bitmaps (padded)
__device__ volatile unsigned g_arrive[BQ];         // zero-init; reset per run
__device__ double            g_part[TOTB];
__device__ unsigned          g_ctr = 0;

__device__ __forceinline__ unsigned pack32(const float4* p)
{
    float4 v[8];
    #pragma unroll
    for (int q = 0; q < 8; ++q) v[q] = p[q];
    unsigned bits = 0;
    #pragma unroll
    for (int q = 0; q < 8; ++q) {
        bits |= (v[q].x > 0.5f ? 1u : 0u) << (q * 4 + 0);
        bits |= (v[q].y > 0.5f ? 1u : 0u) << (q * 4 + 1);
        bits |= (v[q].z > 0.5f ? 1u : 0u) << (q * 4 + 2);
        bits |= (v[q].w > 0.5f ? 1u : 0u) << (q * 4 + 3);
    }
    return bits;
}

// ---------------------------------------------------------------------------
// Single kernel. Warp (g,w) owns raw tag column t=16g+w: gather starts at
// entry with zero prep dependencies. grid=(GS,BQ)x512.
// ---------------------------------------------------------------------------
__global__ void __launch_bounds__(NTH)
lrl_all(const float* __restrict__ scores, const float* __restrict__ M,
        const float* __restrict__ api,   const int*   __restrict__ preds,
        float* __restrict__ out)
{
    const int g    = blockIdx.x;
    const int b    = blockIdx.y;
    const int tid  = threadIdx.x;
    const int wid  = tid >> 5;
    const int lane = tid & 31;

    __shared__ float         s_sc[NN];
    __shared__ float         s_il[NN];
    __shared__ int           s_mbits[MAXMB];
    __shared__ int           s_first[MAXMB];
    __shared__ unsigned      s_rows[MAXMB][5];
    __shared__ unsigned      s_mjlo[NN], s_mjhi[NN];
    __shared__ unsigned      s_amlo[NN], s_amhi[NN];
    __shared__ unsigned char s_et[MAXMB * NN];
    __shared__ float         s_cU[NN];
    __shared__ float         s_S[NN + 1], s_C[NN + 1];
    __shared__ int           s_mcnt;
    __shared__ float         s_invMc;
    __shared__ float         s_red[16];
    __shared__ int           s_last;
    __shared__ double        s_dred[TOTB];

    // ---- P0: everything issues at entry --------------------------------------
    const int   t  = g * 16 + wid;                 // this warp's tag column
    const float mt = M[b * TT + t];                // broadcast (gates the store)
    int pc[5];
    #pragma unroll
    for (int c = 0; c < 5; ++c)
        pc[c] = preds[b * NN + c * 32 + lane];     // coalesced
    float av[5];
    #pragma unroll
    for (int c = 0; c < 5; ++c)
        av[c] = api[(size_t)pc[c] * TT + t];       // unconditional gather (MLP)

    unsigned mw = 0;
    if (wid == 0 && lane < NWU)
        mw = pack32((const float4*)(M + b * TT + lane * 32));
    if (tid >= 32 && tid < 192)  s_sc[tid - 32]  = scores[b * NN + (tid - 32)];
    if (tid >= 192 && tid < 352) s_il[tid - 192] = 1.0f / log2f((float)(tid - 192 + 2));
    if (tid >= 352) {
        const int i = tid - 352;                   // 160 threads
        s_mjlo[i] = 0u; s_mjhi[i] = 0u;
        s_amlo[i] = 0u; s_amhi[i] = 0u;
    }

    // ballots + store (warp-uniform predicate)
    if (mt > 0.5f) {
        const unsigned b0 = __ballot_sync(0xffffffffu, av[0] > 0.5f);
        const unsigned b1 = __ballot_sync(0xffffffffu, av[1] > 0.5f);
        const unsigned b2 = __ballot_sync(0xffffffffu, av[2] > 0.5f);
        const unsigned b3 = __ballot_sync(0xffffffffu, av[3] > 0.5f);
        const unsigned b4 = __ballot_sync(0xffffffffu, av[4] > 0.5f);
        if (lane == 0) {
            g_rowsT[b][t][0] = b0;
            g_rowsT[b][t][1] = b1;
            g_rowsT[b][t][2] = b2;
            g_rowsT[b][t][3] = b3;
            g_rowsT[b][t][4] = b4;
            __threadfence();                       // writer fences (canon pattern)
        }
    }

    // warp0: mbits scan on register words (no smem round trip)
    if (wid == 0) {
        const int cnt = __popc(mw);
        int inc = cnt;
        #pragma unroll
        for (int o = 1; o < 32; o <<= 1) {
            const int v = __shfl_up_sync(0xffffffffu, inc, o);
            if (lane >= o) inc += v;
        }
        int off = inc - cnt;                       // exclusive prefix
        const int total = __shfl_sync(0xffffffffu, inc, 31);
        unsigned mm = mw;
        while (mm) {
            const int bp = __ffs(mm) - 1;
            mm &= mm - 1;
            if (off < MAXMB) s_mbits[off] = lane * 32 + bp;
            ++off;
        }
        if (lane == 0) {
            s_mcnt  = (total > MAXMB) ? MAXMB : total;
            s_invMc = 1.0f / (float)(total + 1);
        }
    }
    __syncthreads();                               // bar1: stores fenced, smem staged
    if (tid == 0) atomicAdd((unsigned*)&g_arrive[b], 1u);

    // ---- pair decode + lam (overlaps other blocks' production) ---------------
    int   pri = 0, prj = 0, prv = 0;
    float plam = 0.0f;
    {
        const int chunk = (PAIRS + GS - 1) / GS;   // 398
        const int p  = g * chunk + tid;
        const int p1 = min(g * chunk + chunk, PAIRS);
        prv = (p < p1);
        if (prv) {
            int j = (int)((1.0f + sqrtf(8.0f * (float)p + 1.0f)) * 0.5f);
            while (((j * (j - 1)) >> 1) > p) --j;
            while (((j * (j + 1)) >> 1) <= p) ++j;
            pri = p - ((j * (j - 1)) >> 1);
            prj = j;
            plam = 1.0f / (1.0f + expf(s_sc[pri] - s_sc[prj]));
        }
    }

    // ---- spin: all GS blocks of this batch have published ---------------------
    if (tid == 0) {
        while (g_arrive[b] < GS) { /* volatile poll */ }
        __threadfence();                           // acquire
    }
    __syncthreads();                               // bar2

    const int mcnt = s_mcnt;

    // ---- SegA: fused bitmap read (L2) + first occurrence -----------------------
    if (tid < mcnt) {
        const int tm = s_mbits[tid];
        const unsigned r0 = g_rowsT[b][tm][0];
        const unsigned r1 = g_rowsT[b][tm][1];
        const unsigned r2 = g_rowsT[b][tm][2];
        const unsigned r3 = g_rowsT[b][tm][3];
        const unsigned r4 = g_rowsT[b][tm][4];
        s_rows[tid][0] = r0; s_rows[tid][1] = r1; s_rows[tid][2] = r2;
        s_rows[tid][3] = r3; s_rows[tid][4] = r4;
        int first = 1000;
        if (r4) first = 128 + __ffs(r4) - 1;
        if (r3) first =  96 + __ffs(r3) - 1;
        if (r2) first =  64 + __ffs(r2) - 1;
        if (r1) first =  32 + __ffs(r1) - 1;
        if (r0) first =   0 + __ffs(r0) - 1;
        s_first[tid] = first;
    }
    __syncthreads();                               // bar3

    // ---- SegB: mj scatter (all warps) ; cU (w0-4) || alive e-fill (w5-15) ------
    for (int task = wid; task < mcnt * 5; task += 16) {
        const int m  = task / 5;
        const int jw = task - m * 5;
        const unsigned word = s_rows[m][jw];
        if ((word >> lane) & 1u) {
            const int j = jw * 32 + lane;
            if (m < 32) atomicOr(&s_mjlo[j], 1u << m);
            else        atomicOr(&s_mjhi[j], 1u << (m - 32));
        }
    }
    if (wid < 5) {
        if (tid < NN) {
            int cu = 0;
            #pragma unroll 4
            for (int m = 0; m < mcnt; ++m) cu += (s_first[m] > tid);
            s_cU[tid] = (float)cu;
        }
    } else {
        for (int m = wid - 5; m < mcnt; m += 11) {
            const int first = s_first[m];
            const int iend  = min(first + 1, NN - 1);
            for (int i = lane; i <= iend; i += 32) {
                int nxt = 1000;
                const int r = i + 1;
                if (r < NN) {
                    int wd = r >> 5;
                    unsigned bits = s_rows[m][wd] & (0xffffffffu << (r & 31));
                    while (!bits && ++wd < 5) bits = s_rows[m][wd];
                    if (bits) nxt = wd * 32 + __ffs(bits) - 1;
                }
                const int e = (i == 0 && first <= NN - 2) ? 0 : min(nxt + 1, NN);
                s_et[m * NN + i] = (unsigned char)e;
                if (m < 32) atomicOr(&s_amlo[i], 1u << m);
                else        atomicOr(&s_amhi[i], 1u << (m - 32));
            }
        }
    }
    __syncthreads();                               // bar4

    // ---- SegC: single-warp serial 5-chunk S/C scan (no fixup barrier) ----------
    if (wid == 0) {
        float cS = 0.0f, cC = 0.0f;
        #pragma unroll
        for (int c = 0; c < 5; ++c) {
            const int idx = c * 32 + lane;
            float a = s_il[idx];
            float d = s_cU[idx] * s_il[idx];
            #pragma unroll
            for (int o = 1; o < 32; o <<= 1) {
                const float ta = __shfl_up_sync(0xffffffffu, a, o);
                const float td = __shfl_up_sync(0xffffffffu, d, o);
                if (lane >= o) { a += ta; d += td; }
            }
            s_S[idx + 1] = cS + a;
            s_C[idx + 1] = cC + d;
            cS += __shfl_sync(0xffffffffu, a, 31);
            cC += __shfl_sync(0xffffffffu, d, 31);
        }
        if (lane == 0) { s_S[0] = 0.0f; s_C[0] = 0.0f; }
    }
    __syncthreads();                               // bar5

    // ---- PG: one pair per thread; sparse alive∩¬tag[j] loop ---------------------
    float acc = 0.0f;
    if (prv) {
        const int i = pri, j = prj;
        const float Si = s_S[i], Sj = s_S[j];
        unsigned long long w =
              (unsigned long long)(s_amlo[i] & ~s_mjlo[j])
            | ((unsigned long long)(s_amhi[i] & ~s_mjhi[j]) << 32);
        float acc2 = 0.0f;
        while (w) {
            const int m = __ffsll(w) - 1;
            w &= w - 1;
            const int e = s_et[m * NN + i];
            acc2 += fminf(s_S[e], Sj) - Si;
        }
        acc = plam * ((s_C[j] - s_C[i]) - acc2);
    }

    // ---- block reduce + deterministic finalize -----------------------------------
    #pragma unroll
    for (int off = 16; off; off >>= 1)
        acc += __shfl_down_sync(0xffffffffu, acc, off);
    if (lane == 0) s_red[wid] = acc;
    __syncthreads();
    if (tid < 32) {
        float v = (tid < 16) ? s_red[tid] : 0.0f;
        #pragma unroll
        for (int off = 8; off; off >>= 1)
            v += __shfl_down_sync(0xffffffffu, v, off);
        if (tid == 0) {
            g_part[b * GS + g] = (double)v * (double)s_invMc;
            __threadfence();
            const unsigned old = atomicInc(&g_ctr, TOTB - 1);   // wraps to 0
            s_last = (old == TOTB - 1);
        }
    }
    __syncthreads();

    if (s_last) {
        if (tid < BQ) *((unsigned*)&g_arrive[tid]) = 0;   // reset for next replay
        if (tid == 0) __threadfence();
        __syncthreads();
        if (tid < TOTB) s_dred[tid] = g_part[tid];
        __syncthreads();
        if (tid < 64) s_dred[tid] += s_dred[tid + 64];
        __syncthreads();
        if (tid < 32) {
            double v = s_dred[tid] + s_dred[tid + 32];
            #pragma unroll
            for (int off = 16; off; off >>= 1)
                v += __shfl_down_sync(0xffffffffu, v, off);
            if (tid == 0)
                out[0] = (float)(v / (double)((NN + 1) * BQ));
        }
    }
}

// ---------------------------------------------------------------------------
extern "C" void kernel_launch(void* const* d_in, const int* in_sizes, int n_in,
                              void* d_out, int out_size)
{
    const float* y_scores = (const float*)d_in[0];   // (B, N) f32
    const float* M        = (const float*)d_in[1];   // (B, T) f32 {0,1}
    const float* api      = (const float*)d_in[2];   // (NUM_API, T) f32 {0,1}
    const int*   preds    = (const int*)  d_in[3];   // (B, N) i32
    float* out = (float*)d_out;

    lrl_all<<<dim3(GS, BQ), NTH>>>(y_scores, M, api, preds, out);
}